// round 4
// baseline (speedup 1.0000x reference)
#include <cuda_runtime.h>

typedef unsigned long long ull;
typedef long long ll;

#define S_LEN   1024
#define D_DIM   64
#define NPOS    64
#define KT      64                  // keys per smem tile
#define NT      (S_LEN / KT)        // 16
#define THREADS 128
#define ROWS    32                  // rows per CTA (4 threads per row)
#define SCALE_F 0.125f
#define FULLM   0xffffffffu

#define PE_STRIDE 68
#define PE_FLOATS (NPOS * PE_STRIDE)        // 4352 floats; k tile (64*64=4096) reuses it
#define LG_STRIDE 66
#define SMEM_FLOATS (PE_FLOATS + ROWS * LG_STRIDE)
#define SMEM_BYTES  (SMEM_FLOATS * 4)       // 25856 B

__device__ __forceinline__ ull fma2(ull a, ull b, ull c) {
    ull d;
    asm("fma.rn.f32x2 %0, %1, %2, %3;" : "=l"(d) : "l"(a), "l"(b), "l"(c));
    return d;
}
__device__ __forceinline__ float hsum2(ull a) {
    unsigned lo, hi;
    asm("mov.b64 {%0, %1}, %2;" : "=r"(lo), "=r"(hi) : "l"(a));
    return __uint_as_float(lo) + __uint_as_float(hi);
}
__device__ __forceinline__ float sigm(float x) {
    return __fdividef(1.0f, 1.0f + __expf(-x));
}

__global__ void __launch_bounds__(THREADS, 6)
cope_kernel(const float* __restrict__ q, const float* __restrict__ kmat,
            const float* __restrict__ pos_emb, const int* __restrict__ flag_p,
            float* __restrict__ out)
{
    extern __shared__ float smem[];
    float* pe_t  = smem;                       // phase1: pos_emb^T [64][68]; phase2: k tile [64][64]
    float* lgt   = smem + PE_FLOATS;           // [ROWS][66] logits_int

    const int tid  = threadIdx.x;
    const int lane = tid & 31;
    const int lrow = tid >> 2;                 // 0..31: row within CTA
    const int sub  = tid & 3;                  // quad lane: d-slice / key-pair owner
    const unsigned qm = 0xFu << (lane & ~3);   // quad shuffle mask

    const ll  grow = (ll)blockIdx.x * ROWS + lrow;
    const int b    = blockIdx.x >> 5;          // 32 CTAs per batch

    // ---- Phase 0: pos_emb -> smem transposed: pe_t[n][d] = pos_emb[d*64 + n]
    for (int i = tid; i < D_DIM * NPOS; i += THREADS) {
        int d = i >> 6, n = i & 63;
        pe_t[n * PE_STRIDE + d] = pos_emb[i];
    }
    __syncthreads();

    // ---- Phase 1: logits_int[row][n] = base[row]·pos_emb[:,n], quad d-split
    const int flag = *flag_p;
    ull qs[8];                                 // my 16-float q slice (phase 2)
    {
        ull bs[8];                             // my 16-float base slice
        const ulonglong2* bp =
            (const ulonglong2*)((flag ? q : kmat) + grow * D_DIM + sub * 16);
        const ulonglong2* qp =
            (const ulonglong2*)(q + grow * D_DIM + sub * 16);
        #pragma unroll
        for (int j = 0; j < 4; ++j) {
            ulonglong2 v = bp[j]; bs[2*j] = v.x; bs[2*j+1] = v.y;
            ulonglong2 w = qp[j]; qs[2*j] = w.x; qs[2*j+1] = w.y;
        }
        #pragma unroll
        for (int c = 0; c < 8; ++c) {          // 8 chunks of 8 npos
            ull acc[8];
            #pragma unroll
            for (int j = 0; j < 8; ++j) acc[j] = 0ull;
            #pragma unroll
            for (int i = 0; i < 4; ++i) {
                #pragma unroll
                for (int j = 0; j < 8; ++j) {
                    ulonglong2 v = *(const ulonglong2*)
                        (pe_t + (c * 8 + j) * PE_STRIDE + sub * 16 + i * 4);
                    acc[j] = fma2(bs[2*i],     v.x, acc[j]);
                    acc[j] = fma2(bs[2*i + 1], v.y, acc[j]);
                }
            }
            float dd[8];
            #pragma unroll
            for (int j = 0; j < 8; ++j) dd[j] = hsum2(acc[j]);
            #pragma unroll
            for (int j = 0; j < 8; ++j) dd[j] += __shfl_xor_sync(FULLM, dd[j], 1);
            #pragma unroll
            for (int j = 0; j < 8; ++j) dd[j] += __shfl_xor_sync(FULLM, dd[j], 2);
            // thread 'sub' owns npos c*8 + sub*2 + {0,1}
            lgt[lrow * LG_STRIDE + c * 8 + sub * 2]     = dd[sub * 2];
            lgt[lrow * LG_STRIDE + c * 8 + sub * 2 + 1] = dd[sub * 2 + 1];
        }
        if (sub == 0) lgt[lrow * LG_STRIDE + 64] = 0.0f;   // guard for ceil at pos==63
    }

    // ---- Phase 2: reverse key-tile sweep; carry replicated across the quad
    float* ktile = pe_t;                        // reuse (barrier below orders it)
    float  carry = 0.0f;
    bool   flushed = false;

    for (int t = NT - 1; t >= 0; --t) {
        bool done = carry >= 63.0f;            // quad-uniform (bit-identical carry)
        if (done && !flushed) {
            // all remaining keys [0, (t+1)*KT) get logits_int[row][63]
            float v = lgt[lrow * LG_STRIDE + 63];
            float4 vv = make_float4(v, v, v, v);
            float* dst = out + grow * S_LEN;
            const int cnt = (t + 1) * KT;
            for (int c = sub * 4; c < cnt; c += 16) *(float4*)(dst + c) = vv;
            flushed = true;
        }
        if (__syncthreads_and(done)) break;

        // cooperative k-tile load: keys [t*KT, t*KT+64) x 64 dims, linear
        {
            const float4* src = (const float4*)(kmat + ((ll)b * S_LEN + t * KT) * D_DIM);
            float4* dst = (float4*)ktile;
            #pragma unroll
            for (int i = 0; i < 8; ++i) dst[tid + i * THREADS] = src[tid + i * THREADS];
        }
        __syncthreads();

        if (!done) {
            const float* lr = lgt + lrow * LG_STRIDE;
            for (int g = 7; g >= 0; --g) {     // 8-key groups, descending
                const float* kt = ktile + g * 8 * D_DIM + sub * 16;
                ull acc[8];
                #pragma unroll
                for (int j = 0; j < 8; ++j) acc[j] = 0ull;
                #pragma unroll
                for (int i = 0; i < 4; ++i) {
                    #pragma unroll
                    for (int j = 0; j < 8; ++j) {
                        ulonglong2 v = *(const ulonglong2*)(kt + j * D_DIM + i * 4);
                        acc[j] = fma2(qs[2*i],     v.x, acc[j]);
                        acc[j] = fma2(qs[2*i + 1], v.y, acc[j]);
                    }
                }
                float dd[8];
                #pragma unroll
                for (int j = 0; j < 8; ++j) dd[j] = hsum2(acc[j]);
                #pragma unroll
                for (int j = 0; j < 8; ++j) dd[j] += __shfl_xor_sync(qm, dd[j], 1);
                #pragma unroll
                for (int j = 0; j < 8; ++j) dd[j] += __shfl_xor_sync(qm, dd[j], 2);
                float gg[8];
                #pragma unroll
                for (int j = 0; j < 8; ++j) gg[j] = sigm(dd[j] * SCALE_F);

                float vlo = 0.0f, vhi = 0.0f;
                #pragma unroll
                for (int j = 7; j >= 0; --j) {
                    carry += gg[j];            // identical in all 4 quad lanes
                    if ((j >> 1) == sub) {     // predicated: only my 2 keys gather
                        float pos = fminf(carry, 63.0f);
                        float pf  = floorf(pos);
                        int   ip  = (int)pf;
                        float w   = pos - pf;
                        float lf  = lr[ip];
                        float lc  = lr[ip + 1];
                        float val = lc * w + lf * (1.0f - w);
                        if (j & 1) vhi = val; else vlo = val;
                    }
                }
                *(float2*)(out + grow * S_LEN + t * KT + g * 8 + sub * 2) =
                    make_float2(vlo, vhi);
            }
        }
    }
}

extern "C" void kernel_launch(void* const* d_in, const int* in_sizes, int n_in,
                              void* d_out, int out_size) {
    const float* q    = (const float*)d_in[0];
    const float* k    = (const float*)d_in[1];
    // d_in[2] = v (unused in mode 0)
    const float* pe   = (const float*)d_in[3];
    // d_in[4] = w_k (unused)
    const int*   flag = (const int*)d_in[5];
    float* out = (float*)d_out;

    cudaFuncSetAttribute(cope_kernel, cudaFuncAttributeMaxDynamicSharedMemorySize, SMEM_BYTES);
    const int grid = (32 * S_LEN) / ROWS;      // 1024 CTAs
    cope_kernel<<<grid, THREADS, SMEM_BYTES>>>(q, k, pe, flag, out);
}

// round 5
// speedup vs baseline: 1.8913x; 1.8913x over previous
#include <cuda_runtime.h>

typedef unsigned long long ull;
typedef long long ll;

#define S_LEN   1024
#define D_DIM   64
#define NPOS    64
#define KT      64
#define NT      16
#define THREADS 64                  // 2 warps; thread = row
#define ROWS    64
#define SCALE_F 0.125f
#define FULLM   0xffffffffu

// smem layout (floats):
//   kbuf0 @ 0     : 4096   (16 KB)
//   kbuf1 @ 4096  : 4096   (16 KB)
//   lgt   @ 8192  : 64*66 = 4224
//   stg   @ 12416 : 64*68 = 4352  (per-warp 32*66 staging; aliased as pe_t[64][68] in phase 0/1)
#define LG_STRIDE 66
#define ST_STRIDE 66
#define PE_STRIDE 68
#define SMEM_FLOATS (4096 + 4096 + 4224 + 4352)
#define SMEM_BYTES  (SMEM_FLOATS * 4)       // 67072 B -> 3 CTAs/SM

__device__ __forceinline__ ull fma2(ull a, ull b, ull c) {
    ull d;
    asm("fma.rn.f32x2 %0, %1, %2, %3;" : "=l"(d) : "l"(a), "l"(b), "l"(c));
    return d;
}
__device__ __forceinline__ float hsum2(ull a) {
    unsigned lo, hi;
    asm("mov.b64 {%0, %1}, %2;" : "=r"(lo), "=r"(hi) : "l"(a));
    return __uint_as_float(lo) + __uint_as_float(hi);
}
__device__ __forceinline__ float sigm(float x) {
    return __fdividef(1.0f, 1.0f + __expf(-x));
}
__device__ __forceinline__ void cp16(unsigned dst, const void* src) {
    asm volatile("cp.async.cg.shared.global [%0], [%1], 16;\n" :: "r"(dst), "l"(src));
}

__global__ void __launch_bounds__(THREADS, 3)
cope_kernel(const float* __restrict__ q, const float* __restrict__ kmat,
            const float* __restrict__ pos_emb, const int* __restrict__ flag_p,
            float* __restrict__ out)
{
    extern __shared__ float smem[];
    float* kbuf0 = smem;
    float* kbuf1 = smem + 4096;
    float* lgt   = smem + 8192;
    float* stg   = smem + 12416;
    float* pe_t  = stg;                        // phase 0/1 alias, stride 68

    const int tid  = threadIdx.x;
    const int wid  = tid >> 5;
    const int lane = tid & 31;
    const ll  grow = (ll)blockIdx.x * ROWS + tid;
    const int b    = blockIdx.x >> 4;          // 16 CTAs per batch
    const float* kbatch = kmat + (ll)b * S_LEN * D_DIM;
    float* mylg  = lgt + tid * LG_STRIDE;
    float* mystg = stg + wid * (32 * ST_STRIDE);

    // ---- prefetch tile 15 into kbuf1 (overlaps phases 0/1)
    {
        unsigned d = (unsigned)__cvta_generic_to_shared(kbuf1);
        const float4* src = (const float4*)(kbatch + 15 * KT * D_DIM);
        #pragma unroll
        for (int i = 0; i < 16; ++i)
            cp16(d + (unsigned)(tid + i * 64) * 16u, src + tid + i * 64);
        asm volatile("cp.async.commit_group;\n");
    }

    // ---- Phase 0: pos_emb -> pe_t transposed: pe_t[n][d] = pos_emb[d*64 + n]
    for (int i = tid; i < D_DIM * NPOS; i += THREADS) {
        int d = i >> 6, n = i & 63;
        pe_t[n * PE_STRIDE + d] = pos_emb[i];
    }
    __syncthreads();

    // ---- Phase 1: logits_int[row][n] = base[row]·pos_emb[:,n]
    const int flag = *flag_p;
    ull qp[32];
    {
        const ulonglong2* bp = (const ulonglong2*)((flag ? q : kmat) + grow * D_DIM);
        #pragma unroll
        for (int j = 0; j < 16; ++j) { ulonglong2 v = bp[j]; qp[2*j] = v.x; qp[2*j+1] = v.y; }
    }
    for (int n = 0; n < NPOS; ++n) {
        const ulonglong2* pr = (const ulonglong2*)(pe_t + n * PE_STRIDE);
        ull acc = 0ull;
        #pragma unroll
        for (int j = 0; j < 16; ++j) {
            ulonglong2 v = pr[j];
            acc = fma2(qp[2*j],     v.x, acc);
            acc = fma2(qp[2*j + 1], v.y, acc);
        }
        mylg[n] = hsum2(acc);
    }
    mylg[NPOS] = 0.0f;                          // guard: pos==63 -> w=0 path
    // reload q (gates always use q)
    {
        const ulonglong2* bp = (const ulonglong2*)(q + grow * D_DIM);
        #pragma unroll
        for (int j = 0; j < 16; ++j) { ulonglong2 v = bp[j]; qp[2*j] = v.x; qp[2*j+1] = v.y; }
    }
    __syncthreads();                            // pe_t reads done -> stg reusable

    // ---- Phase 2: reverse tile sweep, double-buffered
    float carry = 0.0f;
    int t = NT - 1;
    for (;;) {
        if (t > 0) {                            // speculative prefetch of tile t-1
            float* nb = ((t - 1) & 1) ? kbuf1 : kbuf0;
            unsigned d = (unsigned)__cvta_generic_to_shared(nb);
            const float4* src = (const float4*)(kbatch + (t - 1) * KT * D_DIM);
            #pragma unroll
            for (int i = 0; i < 16; ++i)
                cp16(d + (unsigned)(tid + i * 64) * 16u, src + tid + i * 64);
            asm volatile("cp.async.commit_group;\n");
            asm volatile("cp.async.wait_group 1;\n");
        } else {
            asm volatile("cp.async.wait_group 0;\n");
        }
        __syncthreads();                        // kbuf[t&1] visible to all

        const float* ktile = (t & 1) ? kbuf1 : kbuf0;
        const int kb = t * KT;
        unsigned sat = __ballot_sync(FULLM, carry >= 63.0f);

        if (sat == FULLM) {
            // warp fully saturated: per-row constant fill of this tile (coalesced)
            for (int r = 0; r < 32; ++r) {
                float v = lgt[(wid * 32 + r) * LG_STRIDE + 63];   // broadcast LDS
                ll orow = (ll)blockIdx.x * ROWS + wid * 32 + r;
                __stcs((float2*)(out + orow * S_LEN + kb) + lane, make_float2(v, v));
            }
        } else {
            for (int kk0 = KT - 8; kk0 >= 0; kk0 -= 8) {
                ull acc[8];
                #pragma unroll
                for (int j = 0; j < 8; ++j) acc[j] = 0ull;
                #pragma unroll
                for (int i = 0; i < 16; ++i) {
                    #pragma unroll
                    for (int j = 0; j < 8; ++j) {
                        ulonglong2 v = *(const ulonglong2*)(ktile + (kk0 + j) * D_DIM + i * 4);
                        acc[j] = fma2(qp[2*i],     v.x, acc[j]);
                        acc[j] = fma2(qp[2*i + 1], v.y, acc[j]);
                    }
                }
                float g[8];
                #pragma unroll
                for (int j = 0; j < 8; ++j)
                    g[j] = sigm(hsum2(acc[j]) * SCALE_F);
                #pragma unroll
                for (int j = 7; j >= 0; --j) {
                    carry += g[j];
                    float pos = fminf(carry, 63.0f);
                    float pf  = floorf(pos);
                    int   ip  = (int)pf;
                    float w   = pos - pf;
                    float lf  = mylg[ip];
                    float lc  = mylg[ip + 1];
                    mystg[lane * ST_STRIDE + kk0 + j] = lc * w + lf * (1.0f - w);
                }
            }
            __syncwarp();
            for (int r = 0; r < 32; ++r) {
                ll orow = (ll)blockIdx.x * ROWS + wid * 32 + r;
                float2 v = *(const float2*)(mystg + r * ST_STRIDE + 2 * lane);
                __stcs((float2*)(out + orow * S_LEN + kb) + lane, v);
            }
            __syncwarp();
        }

        bool alldone = __syncthreads_and(carry >= 63.0f);  // also orders stg/kbuf reuse
        if (alldone || t == 0) break;
        --t;
    }

    // ---- Phase 3: bulk fill of all untouched low tiles [0, t*KT)
    const int kend = t * KT;
    if (kend > 0) {
        for (int r = 0; r < 32; ++r) {
            float v = lgt[(wid * 32 + r) * LG_STRIDE + 63];
            float4 vv = make_float4(v, v, v, v);
            ll orow = (ll)blockIdx.x * ROWS + wid * 32 + r;
            float* dst = out + orow * S_LEN;
            for (int c = 4 * lane; c < kend; c += 128)
                __stcs((float4*)(dst + c), vv);
        }
    }
}

extern "C" void kernel_launch(void* const* d_in, const int* in_sizes, int n_in,
                              void* d_out, int out_size) {
    const float* q    = (const float*)d_in[0];
    const float* k    = (const float*)d_in[1];
    // d_in[2] = v (unused in mode 0)
    const float* pe   = (const float*)d_in[3];
    // d_in[4] = w_k (unused)
    const int*   flag = (const int*)d_in[5];
    float* out = (float*)d_out;

    cudaFuncSetAttribute(cope_kernel, cudaFuncAttributeMaxDynamicSharedMemorySize, SMEM_BYTES);
    const int grid = (32 * S_LEN) / ROWS;      // 512 CTAs
    cope_kernel<<<grid, THREADS, SMEM_BYTES>>>(q, k, pe, flag, out);
}